// round 4
// baseline (speedup 1.0000x reference)
#include <cuda_runtime.h>
#include <cuda_bf16.h>
#include <math.h>

// RotationalConv2D v4 — GB300 sm_103a
// 2 patches/thread, quad channel-split, f-pair FFMA2 accumulators, W staged
// as u64 f-pairs (no per-f dup MOVs), 16 warps/SM via __launch_bounds__(128,4).

#define HDIM 128
#define CCH 16
#define FOUT 32
#define KK 5
#define HO 124
#define WO 124
#define NP (4 * HO * WO)   // 61504
#define TPB 128
#define PPB 64             // patches per block
#define CROW 17            // u64 stride of one (j,c) row (16 fp + 1 pad)

typedef unsigned long long u64;

__device__ __forceinline__ u64 pk2(float lo, float hi) {
    u64 d; asm("mov.b64 %0, {%1, %2};" : "=l"(d) : "f"(lo), "f"(hi)); return d;
}
__device__ __forceinline__ void upk2(float& lo, float& hi, u64 v) {
    asm("mov.b64 {%0, %1}, %2;" : "=f"(lo), "=f"(hi) : "l"(v));
}
__device__ __forceinline__ u64 ffma2(u64 a, u64 b, u64 c) {
    u64 d; asm("fma.rn.f32x2 %0, %1, %2, %3;" : "=l"(d) : "l"(a), "l"(b), "l"(c)); return d;
}

__global__ void __launch_bounds__(TPB, 4)
rotconv4_kernel(const float* __restrict__ in,
                const float* __restrict__ Wg,
                const float* __restrict__ bias,
                float* __restrict__ out)
{
    extern __shared__ float sm[];
    // phase 1: Ws2[25][16][CROW] u64  (f-pairs; (j,c) row = 16 fp + 1 pad)
    // phase 2: reduce buf [64][16][4] u64 (32KB, fits inside the 54.4KB region)

    // --- stage W: u64 fp-slot lo/hi as consecutive floats ---
    for (int i = threadIdx.x; i < 25 * 16 * 32; i += TPB) {
        int j   = i >> 9;          // /512
        int r   = i & 511;
        int c   = r >> 5;
        int t   = r & 31;
        int fp  = t >> 1;
        int par = t & 1;
        sm[((j * 16 + c) * CROW + fp) * 2 + par] = Wg[(2 * fp + par) * 400 + j * 16 + c];
    }
    __syncthreads();

    const int tid  = threadIdx.x;
    const int pp   = tid >> 2;      // 0..31
    const int g    = tid & 3;
    const int base = blockIdx.x * PPB;

    int   poff[2];
    float co[2], si[2], xo[2], yo[2];

    #pragma unroll
    for (int u = 0; u < 2; u++) {
        const int P   = base + pp + 32 * u;          // grid exact: no clamp needed
        const int b   = P / (HO * WO);
        const int rem = P - b * (HO * WO);
        const int ho  = rem / WO;
        const int wo  = rem - ho * WO;
        const int off = ((b * HDIM + ho) * HDIM + wo) * CCH;
        poff[u] = off;
        const float* pbase = in + off;

        float tot = 0.f, sr = 0.f, sc = 0.f;
        #pragma unroll
        for (int r = 0; r < KK; r++) {
            #pragma unroll
            for (int cl = 0; cl < KK; cl++) {
                float4 v = *reinterpret_cast<const float4*>(pbase + (r * HDIM + cl) * CCH + g * 4);
                float s = v.x + v.y + v.z + v.w;
                tot += s;
                sr  += s * (float)r;
                sc  += s * (float)cl;
            }
        }
        tot += __shfl_xor_sync(0xffffffffu, tot, 1);
        tot += __shfl_xor_sync(0xffffffffu, tot, 2);
        sr  += __shfl_xor_sync(0xffffffffu, sr, 1);
        sr  += __shfl_xor_sync(0xffffffffu, sr, 2);
        sc  += __shfl_xor_sync(0xffffffffu, sc, 1);
        sc  += __shfl_xor_sync(0xffffffffu, sc, 2);

        tot += 1e-7f;
        const float cr   = sr / tot;
        const float ccen = sc / tot;
        const float m    = (float)(KK - 1) * 0.5f;
        const float ang  = atan2f(cr - m, ccen - m + 1e-7f);
        const float c_   = __cosf(ang);
        const float s_   = __sinf(ang);
        const float km1  = (float)(KK - 1);
        co[u] = c_;
        si[u] = s_;
        xo[u] = (km1 - (c_ * km1 - s_ * km1)) * 0.5f;
        yo[u] = (km1 - (s_ * km1 + c_ * km1)) * 0.5f;
    }

    const float scale = 1.0f / (1.0f + 1e-7f);

    u64 accA[16], accB[16];
    #pragma unroll
    for (int fp = 0; fp < 16; fp++) { accA[fp] = 0ull; accB[fp] = 0ull; }

    const u64* wsu = reinterpret_cast<const u64*>(sm);

    // --- main loop over 25 target positions ---
    #pragma unroll 1
    for (int jy = 0; jy < KK; jy++) {
        #pragma unroll 1
        for (int jx = 0; jx < KK; jx++) {
            const float gx = (float)jx;
            const float gy = (float)jy;

            // bilinear rot for this lane's 4 channels, both patches
            u64 rdA[4], rdB[4];
            #pragma unroll
            for (int u = 0; u < 2; u++) {
                const float sx  = (co[u] * gx - si[u] * gy + xo[u]) * scale;
                const float sy  = (si[u] * gx + co[u] * gy + yo[u]) * scale;
                const float x0f = floorf(sx);
                const float y0f = floorf(sy);
                const float wx  = sx - x0f;
                const float wy  = sy - y0f;
                const int   x0  = (int)x0f;
                const int   y0  = (int)y0f;
                const float tw[4] = { (1.f - wx) * (1.f - wy),
                                      wx * (1.f - wy),
                                      (1.f - wx) * wy,
                                      wx * wy };
                float a0 = 0.f, a1 = 0.f, a2 = 0.f, a3 = 0.f;
                #pragma unroll
                for (int t = 0; t < 4; t++) {
                    const int xi = x0 + (t & 1);
                    const int yi = y0 + (t >> 1);
                    if (xi >= 0 && xi < KK && yi >= 0 && yi < KK) {
                        const float4 v = *reinterpret_cast<const float4*>(
                            in + poff[u] + (yi * HDIM + xi) * CCH + g * 4);
                        const float w = tw[t];
                        a0 += w * v.x;
                        a1 += w * v.y;
                        a2 += w * v.z;
                        a3 += w * v.w;
                    }
                }
                if (u == 0) {
                    rdA[0] = pk2(a0, a0); rdA[1] = pk2(a1, a1);
                    rdA[2] = pk2(a2, a2); rdA[3] = pk2(a3, a3);
                } else {
                    rdB[0] = pk2(a0, a0); rdB[1] = pk2(a1, a1);
                    rdB[2] = pk2(a2, a2); rdB[3] = pk2(a3, a3);
                }
            }

            // GEMM: W f-pairs straight from smem, FFMA2 = 2 MACs
            const int j = jy * KK + jx;
            #pragma unroll
            for (int c = 0; c < 4; c++) {
                const u64* wrow = wsu + (j * 16 + (g * 4 + c)) * CROW;
                const u64 ra = rdA[c];
                const u64 rb = rdB[c];
                #pragma unroll
                for (int q = 0; q < 8; q++) {            // 8 x LDS.128 (2 fp each)
                    const ulonglong2 w2 = reinterpret_cast<const ulonglong2*>(wrow)[q];
                    accA[2 * q]     = ffma2(w2.x, ra, accA[2 * q]);
                    accB[2 * q]     = ffma2(w2.x, rb, accB[2 * q]);
                    accA[2 * q + 1] = ffma2(w2.y, ra, accA[2 * q + 1]);
                    accB[2 * q + 1] = ffma2(w2.y, rb, accB[2 * q + 1]);
                }
            }
        }
    }

    // --- quad (channel) reduction via smem transpose ---
    __syncthreads();
    u64* redu = reinterpret_cast<u64*>(sm);   // [64][16][4] u64 = 32KB
    #pragma unroll
    for (int fp = 0; fp < 16; fp++) {
        redu[((pp)      * 16 + fp) * 4 + g] = accA[fp];
        redu[((pp + 32) * 16 + fp) * 4 + g] = accB[fp];
    }
    __syncthreads();

    // finalize: thread -> patch p = tid>>1, f-half = tid&1 (16 outputs)
    const int p    = tid >> 1;
    const int half = tid & 1;
    float* op = out + (base + p) * FOUT + half * 16;
    #pragma unroll
    for (int k = 0; k < 16; k += 4) {
        float res[4];
        #pragma unroll
        for (int q = 0; q < 4; q++) {
            const int f  = half * 16 + k + q;
            const int fp = f >> 1;
            const int se = f & 1;
            float s = 0.f;
            #pragma unroll
            for (int gg = 0; gg < 4; gg++) {
                float lo, hi;
                upk2(lo, hi, redu[(p * 16 + fp) * 4 + gg]);
                s += se ? hi : lo;
            }
            res[q] = s + __ldg(bias + f);
        }
        float4 o;
        o.x = res[0]; o.y = res[1]; o.z = res[2]; o.w = res[3];
        *reinterpret_cast<float4*>(op + k) = o;
    }
}

extern "C" void kernel_launch(void* const* d_in, const int* in_sizes, int n_in,
                              void* d_out, int out_size)
{
    const float* in   = (const float*)d_in[0];   // [4,128,128,16]
    const float* Wg   = (const float*)d_in[1];   // [32,5,5,16]
    const float* bias = (const float*)d_in[2];   // [32]
    float* out = (float*)d_out;                  // [4,124,124,32]

    const int smem = 25 * 16 * CROW * 8;         // 54400 B
    cudaFuncSetAttribute(rotconv4_kernel,
                         cudaFuncAttributeMaxDynamicSharedMemorySize, smem);

    const int nblocks = NP / PPB;                // 961
    rotconv4_kernel<<<nblocks, TPB, smem>>>(in, Wg, bias, out);
}